// round 4
// baseline (speedup 1.0000x reference)
#include <cuda_runtime.h>
#include <cuda_fp16.h>

// Problem constants
#define PN 4096          // rows of M (and of K)
#define PV 8192          // cols of M
#define PNV ((size_t)PN * (size_t)PV)
#define C0 0.9524187f    // midpoint of [exp(-0.1), 1]; K - C0 fits fp16 with ~8e-6 rel err
#define SALPHA 0.1f
#define SEPS 1e-9f
#define NITER 100

#define ROWCH 128                    // row chunks for the column pass
#define ROWS_PER_CH (PN / ROWCH)     // 32 rows per chunk

// ---------------- device scratch (allocation-free: static globals) -----------
__device__ __half g_Kh[PNV];             // K - C0, row-major [N][V]  (64 MB)
__device__ float  g_part[(size_t)ROWCH * PV]; // col-pass partials     (4 MB)
__device__ float  g_u[PN];
__device__ float  g_v[PV];

// ---------------- init: u0 = 1/N, zero loss accumulator ----------------------
__global__ void init_kernel(float* __restrict__ out0) {
    int i = blockIdx.x * blockDim.x + threadIdx.x;
    if (i < PN) g_u[i] = 1.0f / PN;
    if (i == 0) *out0 = 0.0f;
}

// ---------------- setup: Kh = exp(-0.1 M) - C0, fp16, elementwise ------------
// 8 elements per thread. grid = PNV/8/256 blocks.
__global__ void setup_kernel(const float* __restrict__ M) {
    size_t e = ((size_t)blockIdx.x * blockDim.x + threadIdx.x) * 8;
    float4 m0 = *(const float4*)(M + e);
    float4 m1 = *(const float4*)(M + e + 4);
    __half2 h[4];
    h[0] = __floats2half2_rn(__expf(-SALPHA * m0.x) - C0, __expf(-SALPHA * m0.y) - C0);
    h[1] = __floats2half2_rn(__expf(-SALPHA * m0.z) - C0, __expf(-SALPHA * m0.w) - C0);
    h[2] = __floats2half2_rn(__expf(-SALPHA * m1.x) - C0, __expf(-SALPHA * m1.y) - C0);
    h[3] = __floats2half2_rn(__expf(-SALPHA * m1.z) - C0, __expf(-SALPHA * m1.w) - C0);
    *(uint4*)(g_Kh + e) = *(const uint4*)h;
}

// ---------------- col pass stage 1: partial[chunk][j] = sum_{i in chunk} K_ij u_i
// Transpose-free: block = 2048 adjacent columns x one 32-row chunk.
// Each thread owns 8 adjacent columns (one uint4 of halfs per row) -> coalesced.
// grid (PV/2048 = 4, ROWCH = 128), block 256.
__global__ void colpass_partial_kernel() {
    int colbase = blockIdx.x * 2048 + threadIdx.x * 8;
    int row0 = blockIdx.y * ROWS_PER_CH;
    const __half* kp = g_Kh + (size_t)row0 * PV + colbase;
    float acc[8];
#pragma unroll
    for (int k = 0; k < 8; k++) acc[k] = 0.0f;
#pragma unroll 4
    for (int r = 0; r < ROWS_PER_CH; r++) {
        float u = g_u[row0 + r];                       // warp-broadcast, L1-hit
        uint4 pk = *(const uint4*)(kp + (size_t)r * PV);
        const __half2* h = (const __half2*)&pk;
        float2 f0 = __half22float2(h[0]);
        float2 f1 = __half22float2(h[1]);
        float2 f2 = __half22float2(h[2]);
        float2 f3 = __half22float2(h[3]);
        acc[0] += (f0.x + C0) * u;  acc[1] += (f0.y + C0) * u;
        acc[2] += (f1.x + C0) * u;  acc[3] += (f1.y + C0) * u;
        acc[4] += (f2.x + C0) * u;  acc[5] += (f2.y + C0) * u;
        acc[6] += (f3.x + C0) * u;  acc[7] += (f3.y + C0) * u;
    }
    float* p = g_part + (size_t)blockIdx.y * PV + colbase;
    *(float4*)(p)     = make_float4(acc[0], acc[1], acc[2], acc[3]);
    *(float4*)(p + 4) = make_float4(acc[4], acc[5], acc[6], acc[7]);
}

// ---------------- col pass stage 2: v_j = b / (sum_c partial[c][j] + eps) ----
// 8192 threads, one column each; reads are coalesced across threads.
__global__ void colpass_reduce_kernel() {
    int j = blockIdx.x * blockDim.x + threadIdx.x;
    float s = 0.0f;
#pragma unroll 8
    for (int c = 0; c < ROWCH; c++) s += g_part[(size_t)c * PV + j];
    g_v[j] = (1.0f / PV) / (s + SEPS);
}

// ---------------- row pass: u_i = a / (sum_j K_ij v_j + eps) -----------------
// warp per row of K (row-major -> coalesced). 4096 warps = 512 blocks of 256.
__global__ void rowpass_kernel() {
    int warp = (blockIdx.x * blockDim.x + threadIdx.x) >> 5;
    int lane = threadIdx.x & 31;
    const __half* kr = g_Kh + (size_t)warp * PV;
    float acc = 0.0f;
#pragma unroll 4
    for (int it = 0; it < PV / 256; it++) {
        int base = it * 256 + lane * 8;
        uint4 pk = *(const uint4*)(kr + base);
        float4 v0 = *(const float4*)(g_v + base);
        float4 v1 = *(const float4*)(g_v + base + 4);
        const __half2* h = (const __half2*)&pk;
        float2 f0 = __half22float2(h[0]);
        float2 f1 = __half22float2(h[1]);
        float2 f2 = __half22float2(h[2]);
        float2 f3 = __half22float2(h[3]);
        acc += (f0.x + C0) * v0.x + (f0.y + C0) * v0.y
             + (f1.x + C0) * v0.z + (f1.y + C0) * v0.w
             + (f2.x + C0) * v1.x + (f2.y + C0) * v1.y
             + (f3.x + C0) * v1.z + (f3.y + C0) * v1.w;
    }
#pragma unroll
    for (int o = 16; o; o >>= 1) acc += __shfl_xor_sync(0xFFFFFFFFu, acc, o);
    if (lane == 0) g_u[warp] = (1.0f / PN) / (acc + SEPS);
}

// ---------------- final: transp = u * exp(-0.1 M) * v^T; loss = sum(t*M) -----
// Exact K from M for full output precision. out[0] = loss, out[1..] = transp.
__global__ void final_kernel(const float* __restrict__ M, float* __restrict__ out) {
    size_t e = ((size_t)blockIdx.x * blockDim.x + threadIdx.x) * 4;
    int row = (int)(e >> 13);             // V = 8192 = 2^13
    int col = (int)(e & (PV - 1));
    float4 m = *(const float4*)(M + e);
    float u = g_u[row];
    float4 v = *(const float4*)(g_v + col);
    float t0 = u * __expf(-SALPHA * m.x) * v.x;
    float t1 = u * __expf(-SALPHA * m.y) * v.y;
    float t2 = u * __expf(-SALPHA * m.z) * v.z;
    float t3 = u * __expf(-SALPHA * m.w) * v.w;
    float* o = out + 1 + e;
    o[0] = t0; o[1] = t1; o[2] = t2; o[3] = t3;
    float local = t0 * m.x + t1 * m.y + t2 * m.z + t3 * m.w;

#pragma unroll
    for (int o2 = 16; o2; o2 >>= 1) local += __shfl_xor_sync(0xFFFFFFFFu, local, o2);
    __shared__ float wsum[8];
    int wid = threadIdx.x >> 5;
    if ((threadIdx.x & 31) == 0) wsum[wid] = local;
    __syncthreads();
    if (threadIdx.x == 0) {
        float s = 0.0f;
#pragma unroll
        for (int w = 0; w < 8; w++) s += wsum[w];
        atomicAdd(out, s);
    }
}

extern "C" void kernel_launch(void* const* d_in, const int* in_sizes, int n_in,
                              void* d_out, int out_size) {
    const float* M = (const float*)d_in[0];
    float* out = (float*)d_out;

    init_kernel<<<16, 256>>>(out);
    setup_kernel<<<(int)(PNV / 8 / 256), 256>>>(M);

    for (int it = 0; it < NITER; it++) {
        colpass_partial_kernel<<<dim3(PV / 2048, ROWCH), 256>>>();
        colpass_reduce_kernel<<<PV / 256, 256>>>();
        rowpass_kernel<<<(PN * 32) / 256, 256>>>();
    }

    final_kernel<<<(int)(PNV / 4 / 256), 256>>>(M, out);
}